// round 9
// baseline (speedup 1.0000x reference)
#include <cuda_runtime.h>
#include <cuda_fp16.h>
#include <mma.h>

#define N_NODES 40000
#define D 128
#define N_EDGES 640000
#define HASH_BITS 21
#define HASH_SIZE (1u << HASH_BITS)
#define HASH_MASK (HASH_SIZE - 1u)
#define HKEY_EMPTY 0xFFFFFFFFu
#define SLOTS 96                      // >= max symmetrized degree (Poisson(32), 11 sigma)
#define GEMM_BLOCKS (N_NODES / 64)    // 625

// ---- scratch (~34 MB, no allocations allowed) ----
__device__ __align__(16) unsigned g_hash[HASH_SIZE];
__device__ int g_cnt[N_NODES];                       // count AND bucket cursor
__device__ unsigned g_ent[N_NODES * SLOTS];          // src(16) | hr<<16 | neg<<17
__device__ float g_dinv[N_NODES];
__device__ __align__(16) __half g_Zh[N_NODES * D];   // Z' = dinv .* (x @ W), fp16
__device__ __align__(16) __half g_Wh[D * D];         // 0.5*(W1+W2) fp16
__device__ float g_bias[D];                          // 0.5*(b1+b2)

__device__ __forceinline__ unsigned hash_u32(unsigned key) {
    return (key * 2654435761u) >> (32 - HASH_BITS);
}

// ---------------------------------------------------------------------------
// 1. init: hash -> EMPTY (vectorized), cnt -> 0, fold weights to fp16
// ---------------------------------------------------------------------------
__global__ void k_init(const float* __restrict__ W1, const float* __restrict__ b1,
                       const float* __restrict__ W2, const float* __restrict__ b2) {
    unsigned i = blockIdx.x * blockDim.x + threadIdx.x;
    unsigned stride = gridDim.x * blockDim.x;
    uint4* h4 = reinterpret_cast<uint4*>(g_hash);
    const uint4 e4 = make_uint4(HKEY_EMPTY, HKEY_EMPTY, HKEY_EMPTY, HKEY_EMPTY);
    for (unsigned j = i; j < HASH_SIZE / 4; j += stride) h4[j] = e4;
    for (unsigned j = i; j < N_NODES; j += stride) g_cnt[j] = 0;
    if (i < D * D) g_Wh[i] = __float2half(0.5f * (W1[i] + W2[i]));
    if (i < D) g_bias[i] = 0.5f * (b1[i] + b2[i]);
}

// ---------------------------------------------------------------------------
// 2. pass1: hash-insert edge key; the SAME atomicAdd provides histogram count
//    and bucket cursor, so entries are scattered immediately — no scan pass.
//    Entries written without hr (fixed in pass2; reversals are ~0.04%).
// ---------------------------------------------------------------------------
__global__ void k_pass1(const int* __restrict__ ei) {
    int e = blockIdx.x * blockDim.x + threadIdx.x;
    if (e >= N_EDGES) return;
    unsigned row = (unsigned)ei[e];
    unsigned col = (unsigned)ei[N_EDGES + e];
    unsigned key = row * (unsigned)N_NODES + col;
    unsigned h = hash_u32(key);
    while (true) {
        unsigned prev = atomicCAS(&g_hash[h], HKEY_EMPTY, key);
        if (prev == HKEY_EMPTY || prev == key) break;
        h = (h + 1u) & HASH_MASK;
    }
    int p1 = atomicAdd(&g_cnt[row], 1);
    if (p1 < SLOTS) g_ent[row * SLOTS + p1] = col;              // fwd copy, sign +
    int p2 = atomicAdd(&g_cnt[col], 1);
    if (p2 < SLOTS) g_ent[col * SLOTS + p2] = row | 0x20000u;   // rev copy, sign -
}

// ---------------------------------------------------------------------------
// 3. pass2: probe for reverse key; on the rare hit (~0.04% incl. self-loops)
//    OR the hr bit into every matching entry of both buckets (idempotent —
//    the twin edge writes identical values, so the race is benign).
//    First N_NODES threads also compute dinv.
// ---------------------------------------------------------------------------
__global__ void k_pass2(const int* __restrict__ ei) {
    int e = blockIdx.x * blockDim.x + threadIdx.x;
    if (e < N_NODES) {
        int c = g_cnt[e];
        g_dinv[e] = (c > 0) ? rsqrtf(0.5f * (float)c) : 0.f;
    }
    if (e >= N_EDGES) return;
    unsigned row = (unsigned)ei[e];
    unsigned col = (unsigned)ei[N_EDGES + e];
    unsigned rkey = col * (unsigned)N_NODES + row;
    unsigned h = hash_u32(rkey);
    unsigned v;
    while ((v = g_hash[h]) != HKEY_EMPTY && v != rkey) h = (h + 1u) & HASH_MASK;
    if (v == rkey) {
        int n1 = min(g_cnt[row], SLOTS);
        for (int i = 0; i < n1; i++) {
            unsigned en = g_ent[row * SLOTS + i];
            if ((en & 0xFFFFu) == col) g_ent[row * SLOTS + i] = en | 0x10000u;
        }
        int n2 = min(g_cnt[col], SLOTS);
        for (int i = 0; i < n2; i++) {
            unsigned en = g_ent[col * SLOTS + i];
            if ((en & 0xFFFFu) == row) g_ent[col * SLOTS + i] = en | 0x10000u;
        }
    }
}

// ---------------------------------------------------------------------------
// 4. Z' = dinv .* (x @ W) -> fp16 via wmma (64x128 tile, 8 warps 2x4)
// ---------------------------------------------------------------------------
__global__ void __launch_bounds__(256) k_gemm_tc(const float* __restrict__ x) {
    __shared__ __align__(16) __half sA[64 * 128];    // 16 KB
    __shared__ __align__(16) __half sB[128 * 128];   // 32 KB
    const int tid = threadIdx.x;
    const int warp = tid >> 5;
    const int block_row = blockIdx.x * 64;

    const uint4* Wh4 = reinterpret_cast<const uint4*>(g_Wh);
    uint4* sB4 = reinterpret_cast<uint4*>(sB);
#pragma unroll
    for (int q = 0; q < 8; q++) sB4[tid + 256 * q] = Wh4[tid + 256 * q];

    const float4* X4 = reinterpret_cast<const float4*>(x);
    __half2* sA2 = reinterpret_cast<__half2*>(sA);
#pragma unroll
    for (int q = 0; q < 8; q++) {
        int idx = tid + 256 * q;                       // r*32 + c4
        float4 v = X4[(size_t)block_row * 32 + idx];
        sA2[idx * 2]     = __floats2half2_rn(v.x, v.y);
        sA2[idx * 2 + 1] = __floats2half2_rn(v.z, v.w);
    }
    __syncthreads();

    using namespace nvcuda;
    wmma::fragment<wmma::accumulator, 16, 16, 16, float> c[2][2];
#pragma unroll
    for (int i = 0; i < 2; i++)
#pragma unroll
        for (int j = 0; j < 2; j++) wmma::fill_fragment(c[i][j], 0.f);

    const int wm = (warp >> 2) * 32;
    const int wn = (warp & 3) * 32;

#pragma unroll
    for (int k = 0; k < D; k += 16) {
        wmma::fragment<wmma::matrix_a, 16, 16, 16, __half, wmma::row_major> a[2];
        wmma::fragment<wmma::matrix_b, 16, 16, 16, __half, wmma::row_major> b[2];
        wmma::load_matrix_sync(a[0], sA + (wm) * D + k, D);
        wmma::load_matrix_sync(a[1], sA + (wm + 16) * D + k, D);
        wmma::load_matrix_sync(b[0], sB + k * D + wn, D);
        wmma::load_matrix_sync(b[1], sB + k * D + wn + 16, D);
#pragma unroll
        for (int i = 0; i < 2; i++)
#pragma unroll
            for (int j = 0; j < 2; j++)
                wmma::mma_sync(c[i][j], a[i], b[j], c[i][j]);
    }
    __syncthreads();   // done reading sB; reuse as fp32 scratch

    float* scratch = reinterpret_cast<float*>(sB);
#pragma unroll
    for (int i = 0; i < 2; i++)
#pragma unroll
        for (int j = 0; j < 2; j++)
            wmma::store_matrix_sync(scratch + (wm + 16 * i) * D + wn + 16 * j,
                                    c[i][j], D, wmma::mem_row_major);
    __syncthreads();

    uint2* Z2 = reinterpret_cast<uint2*>(g_Zh);
    const float4* sc4 = reinterpret_cast<const float4*>(scratch);
#pragma unroll
    for (int q = 0; q < 8; q++) {
        int idx = tid + 256 * q;                       // r*32 + c4
        float dv = g_dinv[block_row + (idx >> 5)];
        float4 v = sc4[idx];
        __half2 lo = __floats2half2_rn(v.x * dv, v.y * dv);
        __half2 hi = __floats2half2_rn(v.z * dv, v.w * dv);
        uint2 packed;
        packed.x = *reinterpret_cast<unsigned*>(&lo);
        packed.y = *reinterpret_cast<unsigned*>(&hi);
        Z2[(size_t)block_row * 32 + idx] = packed;
    }
}

// ---------------------------------------------------------------------------
// 5. bucket aggregation: one warp per node; Z' carries dinv[src], so weight
//    is the warp-uniform +-0.5*dinv[u]. 4-way unrolled gathers, fp32 acc.
// ---------------------------------------------------------------------------
__global__ void k_spmm(float* __restrict__ out) {
    int u = blockIdx.x * (blockDim.x >> 5) + (threadIdx.x >> 5);
    int lane = threadIdx.x & 31;
    if (u >= N_NODES) return;

    int cnt = min(g_cnt[u], SLOTS);
    int base = u * SLOTS;
    float du = 0.5f * g_dinv[u];

    const uint2* Z2 = reinterpret_cast<const uint2*>(g_Zh);
    float4 are = make_float4(0.f, 0.f, 0.f, 0.f);
    float4 aim = make_float4(0.f, 0.f, 0.f, 0.f);

    for (int b0 = 0; b0 < cnt; b0 += 32) {
        int idx = b0 + lane;
        unsigned ent = (idx < cnt) ? g_ent[base + idx] : 0u;
        int n = min(32, cnt - b0);
        for (int j0 = 0; j0 < n; j0 += 4) {
            int lim = n - j0;                          // warp-uniform
            unsigned ee[4];
            uint2 zz[4];
#pragma unroll
            for (int t = 0; t < 4; t++) {
                ee[t] = __shfl_sync(0xFFFFFFFFu, ent, j0 + t);
                if (t < lim) zz[t] = Z2[(size_t)(ee[t] & 0xFFFFu) * 32 + lane];
            }
#pragma unroll
            for (int t = 0; t < 4; t++) {
                if (t < lim) {
                    __half2 h0 = *reinterpret_cast<__half2*>(&zz[t].x);
                    __half2 h1 = *reinterpret_cast<__half2*>(&zz[t].y);
                    float2 f0 = __half22float2(h0);
                    float2 f1 = __half22float2(h1);
                    if (ee[t] & 0x10000u) {
                        are.x = fmaf(du, f0.x, are.x); are.y = fmaf(du, f0.y, are.y);
                        are.z = fmaf(du, f1.x, are.z); are.w = fmaf(du, f1.y, are.w);
                    } else {
                        float s = (ee[t] & 0x20000u) ? -du : du;
                        aim.x = fmaf(s, f0.x, aim.x); aim.y = fmaf(s, f0.y, aim.y);
                        aim.z = fmaf(s, f1.x, aim.z); aim.w = fmaf(s, f1.y, aim.w);
                    }
                }
            }
        }
    }

    float4 bias = reinterpret_cast<const float4*>(g_bias)[lane];
    float4* O4 = reinterpret_cast<float4*>(out);
    O4[(size_t)u * 64 + lane] =
        make_float4(are.x + bias.x, are.y + bias.y, are.z + bias.z, are.w + bias.w);
    O4[(size_t)u * 64 + 32 + lane] =
        make_float4(aim.x + bias.x, aim.y + bias.y, aim.z + bias.z, aim.w + bias.w);
}

// ---------------------------------------------------------------------------
extern "C" void kernel_launch(void* const* d_in, const int* in_sizes, int n_in,
                              void* d_out, int out_size) {
    const float* x  = (const float*)d_in[0];
    const int*   ei = (const int*)d_in[1];
    const float* W1 = (const float*)d_in[2];
    const float* b1 = (const float*)d_in[3];
    const float* W2 = (const float*)d_in[4];
    const float* b2 = (const float*)d_in[5];
    float* out = (float*)d_out;

    k_init<<<512, 256>>>(W1, b1, W2, b2);
    k_pass1<<<(N_EDGES + 255) / 256, 256>>>(ei);
    k_pass2<<<(N_EDGES + 255) / 256, 256>>>(ei);
    k_gemm_tc<<<GEMM_BLOCKS, 256>>>(x);
    k_spmm<<<(N_NODES + 15) / 16, 512>>>(out);
}

// round 10
// speedup vs baseline: 1.1275x; 1.1275x over previous
#include <cuda_runtime.h>
#include <cuda_fp16.h>
#include <mma.h>

#define N_NODES 40000
#define D 128
#define N_EDGES 640000
#define HASH_BITS 21
#define HASH_SIZE (1u << HASH_BITS)
#define HASH_MASK (HASH_SIZE - 1u)
#define HKEY_EMPTY 0xFFFFFFFFu
#define SCAN_B 256
#define NSCAN_BLK ((N_NODES + SCAN_B - 1) / SCAN_B)   // 157 (<= SCAN_B)
#define LDA (D + 8)                                    // 136 halves: 16B row skew

// ---- scratch (~25 MB, no allocations allowed) ----
__device__ __align__(16) unsigned g_hash[HASH_SIZE];
__device__ int g_cnt[N_NODES];           // symmetrized incidence count
__device__ int g_off[N_NODES + 1];       // CSR offsets
__device__ int g_next[N_NODES];          // scatter cursors
__device__ int g_bsum[NSCAN_BLK];
__device__ unsigned g_ent[2 * N_EDGES];  // packed: src(16) | has_rev(1)<<16 | neg(1)<<17
__device__ float g_dinv[N_NODES];
__device__ __align__(16) __half g_Zh[N_NODES * D];  // Z' = dinv .* (x @ W), fp16
__device__ __align__(16) __half g_Wh[D * D];        // 0.5*(W1+W2) fp16
__device__ float g_bias[D];                          // 0.5*(b1+b2)

__device__ __forceinline__ unsigned hash_u32(unsigned key) {
    return (key * 2654435761u) >> (32 - HASH_BITS);
}

// ---------------------------------------------------------------------------
// 1. init: hash -> EMPTY (vectorized), cnt -> 0, fold weights to fp16
// ---------------------------------------------------------------------------
__global__ void k_init(const float* __restrict__ W1, const float* __restrict__ b1,
                       const float* __restrict__ W2, const float* __restrict__ b2) {
    unsigned i = blockIdx.x * blockDim.x + threadIdx.x;
    unsigned stride = gridDim.x * blockDim.x;
    uint4* h4 = reinterpret_cast<uint4*>(g_hash);
    const uint4 e4 = make_uint4(HKEY_EMPTY, HKEY_EMPTY, HKEY_EMPTY, HKEY_EMPTY);
    for (unsigned j = i; j < HASH_SIZE / 4; j += stride) h4[j] = e4;
    for (unsigned j = i; j < N_NODES; j += stride) g_cnt[j] = 0;
    if (i < D * D) g_Wh[i] = __float2half(0.5f * (W1[i] + W2[i]));
    if (i < D) g_bias[i] = 0.5f * (b1[i] + b2[i]);
}

// ---------------------------------------------------------------------------
// 2. insert edge keys into hash set + symmetrized incidence histogram
// ---------------------------------------------------------------------------
__global__ void k_insert(const int* __restrict__ ei) {
    int e = blockIdx.x * blockDim.x + threadIdx.x;
    if (e >= N_EDGES) return;
    unsigned row = (unsigned)ei[e];
    unsigned col = (unsigned)ei[N_EDGES + e];
    unsigned key = row * (unsigned)N_NODES + col;
    unsigned h = hash_u32(key);
    while (true) {
        unsigned prev = atomicCAS(&g_hash[h], HKEY_EMPTY, key);
        if (prev == HKEY_EMPTY || prev == key) break;
        h = (h + 1u) & HASH_MASK;
    }
    atomicAdd(&g_cnt[row], 1);
    atomicAdd(&g_cnt[col], 1);
}

// ---------------------------------------------------------------------------
// 3a. per-block sums of g_cnt
// ---------------------------------------------------------------------------
__global__ void k_scan_a() {
    __shared__ int sh[SCAN_B];
    int i = blockIdx.x * SCAN_B + threadIdx.x;
    sh[threadIdx.x] = (i < N_NODES) ? g_cnt[i] : 0;
    __syncthreads();
    for (int s = SCAN_B / 2; s > 0; s >>= 1) {
        if (threadIdx.x < s) sh[threadIdx.x] += sh[threadIdx.x + s];
        __syncthreads();
    }
    if (threadIdx.x == 0) g_bsum[blockIdx.x] = sh[0];
}

// ---------------------------------------------------------------------------
// 3b. per-block exclusive scan; block offset via in-block reduction of g_bsum.
//     dinv folded in.
// ---------------------------------------------------------------------------
__global__ void k_scan_c() {
    __shared__ int sh[SCAN_B];
    __shared__ int s_boff;
    int p = (threadIdx.x < blockIdx.x) ? g_bsum[threadIdx.x] : 0;
    sh[threadIdx.x] = p;
    __syncthreads();
    for (int s = SCAN_B / 2; s > 0; s >>= 1) {
        if (threadIdx.x < s) sh[threadIdx.x] += sh[threadIdx.x + s];
        __syncthreads();
    }
    if (threadIdx.x == 0) s_boff = sh[0];
    __syncthreads();
    int i = blockIdx.x * SCAN_B + threadIdx.x;
    int v = (i < N_NODES) ? g_cnt[i] : 0;
    sh[threadIdx.x] = v;
    __syncthreads();
    for (int s = 1; s < SCAN_B; s <<= 1) {
        int t = (threadIdx.x >= s) ? sh[threadIdx.x - s] : 0;
        __syncthreads();
        sh[threadIdx.x] += t;
        __syncthreads();
    }
    int excl = sh[threadIdx.x] - v + s_boff;
    if (i < N_NODES) {
        g_off[i] = excl;
        g_next[i] = excl;
        g_dinv[i] = (v > 0) ? rsqrtf(0.5f * (float)v) : 0.f;
    }
    if (i == N_NODES - 1) g_off[N_NODES] = excl + v;
}

// ---------------------------------------------------------------------------
// 4. scatter packed CSR entries (probe hash once per directed edge)
// ---------------------------------------------------------------------------
__global__ void k_scatter(const int* __restrict__ ei) {
    int e = blockIdx.x * blockDim.x + threadIdx.x;
    if (e >= N_EDGES) return;
    unsigned row = (unsigned)ei[e];
    unsigned col = (unsigned)ei[N_EDGES + e];
    unsigned rkey = col * (unsigned)N_NODES + row;
    unsigned h = hash_u32(rkey);
    unsigned v;
    while ((v = g_hash[h]) != HKEY_EMPTY && v != rkey) h = (h + 1u) & HASH_MASK;
    unsigned hr = (v == rkey) ? 0x10000u : 0u;
    int p1 = atomicAdd(&g_next[row], 1);
    g_ent[p1] = col | hr;                 // forward copy, sign +
    int p2 = atomicAdd(&g_next[col], 1);
    g_ent[p2] = row | hr | 0x20000u;      // reversed copy, sign -
}

// ---------------------------------------------------------------------------
// 5. Z' = dinv .* (x @ W) -> fp16 via wmma, PADDED smem (LDA=136 halves,
//    16B row skew kills the 8-way bank conflicts seen at ldm=128).
//    32x128 block tile, 8 warps in 2x4 (warp tile 16x32), grid 1250.
//    smem: sA 8704 B + sB 34816 B = 43520 B < 48 KB static limit.
// ---------------------------------------------------------------------------
__global__ void __launch_bounds__(256) k_gemm_tc(const float* __restrict__ x) {
    __shared__ __align__(16) __half sA[32 * LDA];    // 8704 B
    __shared__ __align__(16) __half sB[D * LDA];     // 34816 B
    const int tid = threadIdx.x;
    const int warp = tid >> 5;
    const int block_row = blockIdx.x * 32;

    // W -> sB padded: 2048 uint4; 8/thread. 16 uint4 per 128-col row.
    const uint4* Wh4 = reinterpret_cast<const uint4*>(g_Wh);
#pragma unroll
    for (int q = 0; q < 8; q++) {
        int idx = tid + 256 * q;
        int r = idx >> 4, c8 = idx & 15;
        *reinterpret_cast<uint4*>(sB + r * LDA + c8 * 8) = Wh4[idx];
    }

    // x tile (32x128 f32 = 1024 float4; 4/thread) -> fp16 sA padded
    const float4* X4 = reinterpret_cast<const float4*>(x);
#pragma unroll
    for (int q = 0; q < 4; q++) {
        int idx = tid + 256 * q;                       // r*32 + c4
        int r = idx >> 5, c4 = idx & 31;
        float4 v = X4[(size_t)block_row * 32 + idx];
        __half2* dst = reinterpret_cast<__half2*>(sA + r * LDA + c4 * 4);
        dst[0] = __floats2half2_rn(v.x, v.y);
        dst[1] = __floats2half2_rn(v.z, v.w);
    }
    __syncthreads();

    using namespace nvcuda;
    wmma::fragment<wmma::accumulator, 16, 16, 16, float> c[2];
#pragma unroll
    for (int j = 0; j < 2; j++) wmma::fill_fragment(c[j], 0.f);

    const int wm = (warp >> 2) * 16;   // 0 or 16
    const int wn = (warp & 3) * 32;    // 0,32,64,96

#pragma unroll
    for (int k = 0; k < D; k += 16) {
        wmma::fragment<wmma::matrix_a, 16, 16, 16, __half, wmma::row_major> a;
        wmma::fragment<wmma::matrix_b, 16, 16, 16, __half, wmma::row_major> b[2];
        wmma::load_matrix_sync(a, sA + wm * LDA + k, LDA);
        wmma::load_matrix_sync(b[0], sB + k * LDA + wn, LDA);
        wmma::load_matrix_sync(b[1], sB + k * LDA + wn + 16, LDA);
#pragma unroll
        for (int j = 0; j < 2; j++) wmma::mma_sync(c[j], a, b[j], c[j]);
    }
    __syncthreads();   // done reading sB; reuse as fp32 scratch (32*LDA f32 = 17408 B)

    float* scratch = reinterpret_cast<float*>(sB);
#pragma unroll
    for (int j = 0; j < 2; j++)
        wmma::store_matrix_sync(scratch + wm * LDA + wn + 16 * j, c[j], LDA,
                                wmma::mem_row_major);
    __syncthreads();

    // epilogue: scale row by dinv, convert fp16, store Z' (1024 float4; 4/thread)
    uint2* Z2 = reinterpret_cast<uint2*>(g_Zh);
#pragma unroll
    for (int q = 0; q < 4; q++) {
        int idx = tid + 256 * q;                       // r*32 + c4
        int r = idx >> 5, c4 = idx & 31;
        float dv = g_dinv[block_row + r];
        float4 v = *reinterpret_cast<const float4*>(scratch + r * LDA + c4 * 4);
        __half2 lo = __floats2half2_rn(v.x * dv, v.y * dv);
        __half2 hi = __floats2half2_rn(v.z * dv, v.w * dv);
        uint2 packed;
        packed.x = *reinterpret_cast<unsigned*>(&lo);
        packed.y = *reinterpret_cast<unsigned*>(&hi);
        Z2[(size_t)(block_row + r) * 32 + c4] = packed;
    }
}

// ---------------------------------------------------------------------------
// 6. CSR aggregation: one warp per node; Z' carries dinv[src], so weight is
//    the warp-uniform +-0.5*dinv[u]. 4-way unrolled gathers, fp32 acc.
// ---------------------------------------------------------------------------
__global__ void k_spmm_csr(float* __restrict__ out) {
    int u = blockIdx.x * (blockDim.x >> 5) + (threadIdx.x >> 5);
    int lane = threadIdx.x & 31;
    if (u >= N_NODES) return;

    int start = g_off[u];
    int end = g_off[u + 1];
    float du = 0.5f * g_dinv[u];

    const uint2* Z2 = reinterpret_cast<const uint2*>(g_Zh);
    float4 are = make_float4(0.f, 0.f, 0.f, 0.f);
    float4 aim = make_float4(0.f, 0.f, 0.f, 0.f);

    for (int base = start; base < end; base += 32) {
        int idx = base + lane;
        unsigned ent = (idx < end) ? g_ent[idx] : 0u;
        int n = min(32, end - base);
        for (int j0 = 0; j0 < n; j0 += 4) {
            int lim = n - j0;                          // warp-uniform
            unsigned ee[4];
            uint2 zz[4];
#pragma unroll
            for (int t = 0; t < 4; t++) {
                ee[t] = __shfl_sync(0xFFFFFFFFu, ent, j0 + t);
                if (t < lim) zz[t] = Z2[(size_t)(ee[t] & 0xFFFFu) * 32 + lane];
            }
#pragma unroll
            for (int t = 0; t < 4; t++) {
                if (t < lim) {
                    __half2 h0 = *reinterpret_cast<__half2*>(&zz[t].x);
                    __half2 h1 = *reinterpret_cast<__half2*>(&zz[t].y);
                    float2 f0 = __half22float2(h0);
                    float2 f1 = __half22float2(h1);
                    if (ee[t] & 0x10000u) {
                        are.x = fmaf(du, f0.x, are.x); are.y = fmaf(du, f0.y, are.y);
                        are.z = fmaf(du, f1.x, are.z); are.w = fmaf(du, f1.y, are.w);
                    } else {
                        float s = (ee[t] & 0x20000u) ? -du : du;
                        aim.x = fmaf(s, f0.x, aim.x); aim.y = fmaf(s, f0.y, aim.y);
                        aim.z = fmaf(s, f1.x, aim.z); aim.w = fmaf(s, f1.y, aim.w);
                    }
                }
            }
        }
    }

    float4 bias = reinterpret_cast<const float4*>(g_bias)[lane];
    float4* O4 = reinterpret_cast<float4*>(out);
    O4[(size_t)u * 64 + lane] =
        make_float4(are.x + bias.x, are.y + bias.y, are.z + bias.z, are.w + bias.w);
    O4[(size_t)u * 64 + 32 + lane] =
        make_float4(aim.x + bias.x, aim.y + bias.y, aim.z + bias.z, aim.w + bias.w);
}

// ---------------------------------------------------------------------------
extern "C" void kernel_launch(void* const* d_in, const int* in_sizes, int n_in,
                              void* d_out, int out_size) {
    const float* x  = (const float*)d_in[0];
    const int*   ei = (const int*)d_in[1];
    const float* W1 = (const float*)d_in[2];
    const float* b1 = (const float*)d_in[3];
    const float* W2 = (const float*)d_in[4];
    const float* b2 = (const float*)d_in[5];
    float* out = (float*)d_out;

    k_init<<<512, 256>>>(W1, b1, W2, b2);
    k_insert<<<(N_EDGES + 255) / 256, 256>>>(ei);
    k_scan_a<<<NSCAN_BLK, SCAN_B>>>();
    k_scan_c<<<NSCAN_BLK, SCAN_B>>>();
    k_scatter<<<(N_EDGES + 255) / 256, 256>>>(ei);
    k_gemm_tc<<<N_NODES / 32, 256>>>(x);
    k_spmm_csr<<<(N_NODES + 15) / 16, 512>>>(out);
}